// round 16
// baseline (speedup 1.0000x reference)
#include <cuda_runtime.h>
#include <cuda_bf16.h>
#include <math.h>
#include <stdint.h>

// ---------------------------------------------------------------------------
// IterativeBlock on GB300, compute_103-safe.
// Dense GEMMs + rank projections: warp-level mma.sync tf32 (m16n8k8),
// ldmatrix fragment loads, explicit 3-phase pipeline:
//   ldg(c+1)->regs ; compute(c) ; sts(c+1) ; __syncthreads
// Rank reform: R[t] = P[t] + Q[t-1], [P|Q] from a shift-free KD=1024 GEMM.
// rmsnorm: rank kernels compute s[t] INLINE (ssq of streamed h rows),
// apply at their epilogue, and write g_S for iter/ff.  No k_scale kernel.
// k_iter/k_ff: 64-token tiles, 256 threads, 80KB smem -> 2 CTAs/SM.
// h ping-pongs g_H <-> g_H2.  FF intermediate bf16.
// ---------------------------------------------------------------------------

#define NTOK 16384
#define EPSF 1.1920929e-07f

__device__ float         g_H [NTOK * 1024];
__device__ float         g_H2[NTOK * 1024];
__device__ float         g_S [NTOK];
__device__ float         g_R [NTOK * 128];
__device__ __nv_bfloat16 g_FF[NTOK * 2816];

__device__ __forceinline__ float sigf(float x) { return 1.0f / (1.0f + __expf(-x)); }

__device__ __forceinline__ uint32_t cvt_tf32(float f) {
    uint32_t r; asm("cvt.rna.tf32.f32 %0, %1;" : "=r"(r) : "f"(f)); return r;
}
__device__ __forceinline__ uint32_t s2u(const void* p) {
    return (uint32_t)__cvta_generic_to_shared(p);
}
__device__ __forceinline__ void ldsm4(uint32_t& r0, uint32_t& r1, uint32_t& r2, uint32_t& r3,
                                      uint32_t addr) {
    asm volatile("ldmatrix.sync.aligned.m8n8.x4.shared.b16 {%0,%1,%2,%3}, [%4];"
                 : "=r"(r0), "=r"(r1), "=r"(r2), "=r"(r3) : "r"(addr));
}
__device__ __forceinline__ void mma168(float* c, const uint32_t* a, const uint32_t* b) {
    asm volatile(
        "mma.sync.aligned.m16n8k8.row.col.f32.tf32.tf32.f32 "
        "{%0,%1,%2,%3}, {%4,%5,%6,%7}, {%8,%9}, {%0,%1,%2,%3};"
        : "+f"(c[0]), "+f"(c[1]), "+f"(c[2]), "+f"(c[3])
        : "r"(a[0]), "r"(a[1]), "r"(a[2]), "r"(a[3]), "r"(b[0]), "r"(b[1]));
}

// ---- tile staging / fragment loads ----------------------------------------
// 128-byte ldmatrix blocks = 8 rows x 4 tf32.
//   bidA = ((mi*2+mh)*K8 + k8)*2 + kh,  bidB = (ni*K8 + k8)*2 + r
// Row within a block XOR-swizzled by (bid & 7).
template<int K8>
__device__ __forceinline__ void stA(uint32_t base, int row, int q4, float4 v) {
    int k8 = q4 >> 1, kh = q4 & 1;
    int m8 = row & 7, mh = (row >> 3) & 1, mi = row >> 4;
    int bid = ((mi * 2 + mh) * K8 + k8) * 2 + kh;
    int r = m8 ^ (bid & 7);
    uint32_t addr = base + (uint32_t)(bid * 128 + r * 16);
    asm volatile("st.shared.v4.b32 [%0], {%1,%2,%3,%4};" :: "r"(addr),
                 "r"(cvt_tf32(v.x)), "r"(cvt_tf32(v.y)),
                 "r"(cvt_tf32(v.z)), "r"(cvt_tf32(v.w)) : "memory");
}
template<int K8>
__device__ __forceinline__ void stB(uint32_t base, int n, int q4, float4 v) {
    int k8 = q4 >> 1, r = q4 & 1;
    int n8 = n & 7, ni = n >> 3;
    int bid = (ni * K8 + k8) * 2 + r;
    int rr = n8 ^ (bid & 7);
    uint32_t addr = base + (uint32_t)(bid * 128 + rr * 16);
    asm volatile("st.shared.v4.b32 [%0], {%1,%2,%3,%4};" :: "r"(addr),
                 "r"(cvt_tf32(v.x)), "r"(cvt_tf32(v.y)),
                 "r"(cvt_tf32(v.z)), "r"(cvt_tf32(v.w)) : "memory");
}
template<int K8>
__device__ __forceinline__ void ldA(uint32_t* a, uint32_t base, int k8, int mi, int lane) {
    int j = lane >> 3, mh = j & 1, kh = j >> 1;
    int bid = ((mi * 2 + mh) * K8 + k8) * 2 + kh;
    int r = (lane & 7) ^ (bid & 7);
    ldsm4(a[0], a[1], a[2], a[3], base + (uint32_t)(bid * 128 + r * 16));
}
template<int K8>
__device__ __forceinline__ void ldB(uint32_t* b0, uint32_t* b1, uint32_t base,
                                    int k8, int ni0, int lane) {
    int j = lane >> 3, nio = j >> 1, r = j & 1;
    int bid = ((ni0 + nio) * K8 + k8) * 2 + r;
    int rr = (lane & 7) ^ (bid & 7);
    ldsm4(b0[0], b0[1], b1[0], b1[1], base + (uint32_t)(bid * 128 + rr * 16));
}
__device__ __forceinline__ float4 ldbf4(const __nv_bfloat16* p) {
    uint2 raw = *(const uint2*)p;
    __nv_bfloat162 b0 = *(__nv_bfloat162*)&raw.x;
    __nv_bfloat162 b1 = *(__nv_bfloat162*)&raw.y;
    float2 f0 = __bfloat1622float2(b0), f1 = __bfloat1622float2(b1);
    return make_float4(f0.x, f0.y, f1.x, f1.y);
}
__device__ __forceinline__ float4 mul4(float4 v, float s) {
    return make_float4(v.x * s, v.y * s, v.z * s, v.w * s);
}

// ---------------------------------------------------------------------------
// k_rank_m: R[t, 0:NO] = Bmap @ h_t, scaled by s[t] at the epilogue.
// SCALE: s[t] computed INLINE from ssq of the streamed h rows; written to Sout.
// SPLIT4 (PQ): row n -> (n<64 ? B1 : B2) row (n&31), col-half ((n>>5)&1)*1024.
// else: n<32 -> B1 row n; else B2 row n-32 (row length KD).
// BF16SRC: src is bf16 (no scale).  RST: output row stride.
// CTA = 64 tokens, K-chunk 64, 3-phase pipeline.
// 256 threads, 8 warps = 4(wm) x 2(wn).
// ---------------------------------------------------------------------------
template<int NO, int KD, int SRCS, int RST, bool SCALE, bool BF16SRC, bool SPLIT4>
__global__ __launch_bounds__(256)
void k_rank_m(const void* __restrict__ srcv, float* __restrict__ Sout,
              const float* __restrict__ B1, const float* __restrict__ B2,
              float* __restrict__ R) {
    constexpr int K8 = 8;                         // chunk = 64 K
    constexpr int NIW = NO / 16;
    constexpr int NB = NO / 16;
    constexpr int ABYTES = 16384;
    constexpr int BBYTES = NO * 64 * 4;
    constexpr int NC = KD / 64;
    extern __shared__ float sm[];
    __shared__ float sSr[64];
    const uint32_t sbase = s2u(sm);
    const int tid = threadIdx.x, lane = tid & 31, wid = tid >> 5;
    const int wm = wid >> 1, wn = wid & 1;
    const int t0 = blockIdx.x * 64;

    float acc[NIW][4];
#pragma unroll
    for (int j = 0; j < NIW; j++)
#pragma unroll
        for (int i = 0; i < 4; i++) acc[j][i] = 0.0f;

    float ssq[4] = {0.f, 0.f, 0.f, 0.f};
    float4 ar[4], br[NB];

    auto ldg_phase = [&](int c) {
#pragma unroll
        for (int i = 0; i < 4; i++) {             // A: 64 rows x 16 q4
            int idx = tid + i * 256;
            int row = idx >> 4, q4 = idx & 15;
            int tok = t0 + row;
            if (BF16SRC)
                ar[i] = ldbf4((const __nv_bfloat16*)srcv + (size_t)tok * SRCS + c * 64 + q4 * 4);
            else
                ar[i] = __ldg((const float4*)((const float*)srcv +
                              (size_t)tok * SRCS + c * 64) + q4);
        }
#pragma unroll
        for (int i = 0; i < NB; i++) {            // B: NO rows x 16 q4
            int idx = tid + i * 256;
            int n = idx >> 4, q4 = idx & 15;
            const float* Bp;
            if (SPLIT4)
                Bp = ((n < 64) ? B1 : B2) + (size_t)(n & 31) * 2048 + ((n >> 5) & 1) * 1024;
            else
                Bp = (n < 32) ? (B1 + (size_t)n * KD) : (B2 + (size_t)(n - 32) * KD);
            br[i] = __ldg((const float4*)(Bp + c * 64) + q4);
        }
    };
    auto sts_phase = [&](int buf) {
        const uint32_t Ab = sbase + buf * (ABYTES + BBYTES);
        const uint32_t Bb = Ab + ABYTES;
#pragma unroll
        for (int i = 0; i < 4; i++) {
            int idx = tid + i * 256;
            if (SCALE) {
                ssq[i] = fmaf(ar[i].x, ar[i].x, ssq[i]);
                ssq[i] = fmaf(ar[i].y, ar[i].y, ssq[i]);
                ssq[i] = fmaf(ar[i].z, ar[i].z, ssq[i]);
                ssq[i] = fmaf(ar[i].w, ar[i].w, ssq[i]);
            }
            stA<K8>(Ab, idx >> 4, idx & 15, ar[i]);
        }
#pragma unroll
        for (int i = 0; i < NB; i++) {
            int idx = tid + i * 256;
            stB<K8>(Bb, idx >> 4, idx & 15, br[i]);
        }
    };
    auto compute = [&](int buf) {
        const uint32_t Ab = sbase + buf * (ABYTES + BBYTES);
        const uint32_t Bb = Ab + ABYTES;
#pragma unroll
        for (int k8 = 0; k8 < K8; k8++) {
            uint32_t a[4], bf[NIW][2];
            ldA<K8>(a, Ab, k8, wm, lane);
#pragma unroll
            for (int n2 = 0; n2 < NIW; n2 += 2)
                ldB<K8>(bf[n2], bf[n2 + 1], Bb, k8, wn * NIW + n2, lane);
#pragma unroll
            for (int n2 = 0; n2 < NIW; n2++) mma168(acc[n2], a, bf[n2]);
        }
    };

    ldg_phase(0);
    sts_phase(0);
    __syncthreads();
    for (int c = 0; c < NC; c++) {
        int buf = c & 1;
        if (c + 1 < NC) ldg_phase(c + 1);
        compute(buf);
        if (c + 1 < NC) sts_phase(buf ^ 1);
        __syncthreads();
    }

    if (SCALE) {
        // threads tid = g*16 + q4 hold partial ssq for rows {g, g+16, g+32, g+48};
        // reduce over the 16-lane group, lane q4==0 finalizes.
#pragma unroll
        for (int i = 0; i < 4; i++) {
            float v = ssq[i];
#pragma unroll
            for (int off = 8; off; off >>= 1) v += __shfl_xor_sync(0xffffffffu, v, off);
            if ((lane & 15) == 0) {
                int row = (tid >> 4) + i * 16;
                float sc = rsqrtf(v * (1.0f / 1024.0f) + EPSF);
                sSr[row] = sc;
                Sout[t0 + row] = sc;
            }
        }
        __syncthreads();
    }

    const int lr0 = wm * 16 + (lane >> 2);
    const float s0 = SCALE ? sSr[lr0] : 1.0f;
    const float s1 = SCALE ? sSr[lr0 + 8] : 1.0f;
    const int r0 = t0 + lr0, r1 = r0 + 8;
#pragma unroll
    for (int n2 = 0; n2 < NIW; n2++) {
        int o = wn * (NO / 2) + n2 * 8 + 2 * (lane & 3);
        *(float2*)(R + (size_t)r0 * RST + o) = make_float2(acc[n2][0] * s0, acc[n2][1] * s0);
        *(float2*)(R + (size_t)r1 * RST + o) = make_float2(acc[n2][2] * s1, acc[n2][3] * s1);
    }
}

// ---------------------------------------------------------------------------
// k_iter_m: CTA = 64 tokens x block b.  Fused N=256 (n=2o+m: m=0 fg, m=1 gu),
// K=320 = [(h*s)_b slice (256) | Rg(32) | Ru(32)] where
// Rg[t] = PQ[t,0:32]+PQ[t-1,32:64], Ru[t] = PQ[t,64:96]+PQ[t-1,96:128].
// 256 threads = 2(wm) x 4(wn) warps; warp tile 32 rows x 64 outs.
// smem: A 8K x2 + B 32K x2 = 80 KB -> 2 CTAs/SM.
// Epilogue: hout = hin + sigmoid(g)*u  (hin != hout).
// ---------------------------------------------------------------------------
#define ITER_SMEM 81920
__global__ __launch_bounds__(256, 2)
void k_iter_m(const float* __restrict__ hin, const float* __restrict__ sf,
              const float* __restrict__ PQ,
              const float* __restrict__ Wg, const float* __restrict__ Wu,
              const float* __restrict__ Ag, const float* __restrict__ Au,
              float* __restrict__ hout) {
    constexpr int K8 = 4;
    extern __shared__ float sm[];
    __shared__ float sS[65];
    const uint32_t sbase = s2u(sm);
    const uint32_t Ab[2] = { sbase, sbase + 8192 };
    const uint32_t Bb[2] = { sbase + 16384, sbase + 49152 };
    const int tid = threadIdx.x, lane = tid & 31, wid = tid >> 5;
    const int wm = wid >> 2, wn = wid & 3;
    const int t0 = blockIdx.x * 64, b = blockIdx.y;
    const int roff = (b < 4) ? 0 : -1, cbase = (b & 3) * 256, ob = b * 128;

    if (tid < 65) {
        int tk = t0 - 1 + tid;
        sS[tid] = (tk >= 0) ? sf[tk] : 0.0f;
    }
    __syncthreads();

    float acc[2][8][4];
#pragma unroll
    for (int i = 0; i < 2; i++)
#pragma unroll
        for (int j = 0; j < 8; j++)
#pragma unroll
            for (int k = 0; k < 4; k++) acc[i][j][k] = 0.0f;

    float4 ar[2], br[8];

    auto ldg_phase = [&](int c) {
#pragma unroll
        for (int i = 0; i < 2; i++) {             // A: 64 rows x 8 q4
            int idx = tid + i * 256;
            int row = idx >> 3, q4 = idx & 7;
            int tok = t0 + row;
            float4 v = make_float4(0.f, 0.f, 0.f, 0.f);
            if (c < 8) {
                if (roff == 0 || (tok & 2047) != 0)
                    v = __ldg((const float4*)(hin + (size_t)(tok + roff) * 1024
                                              + cbase + c * 32) + q4);
            } else {
                int half = (c == 8) ? 0 : 64;
                float4 p = __ldg((const float4*)(PQ + (size_t)tok * 128 + half) + q4);
                float4 qv = make_float4(0.f, 0.f, 0.f, 0.f);
                if ((tok & 2047) != 0)
                    qv = __ldg((const float4*)(PQ + (size_t)(tok - 1) * 128 + half + 32) + q4);
                v = make_float4(p.x + qv.x, p.y + qv.y, p.z + qv.z, p.w + qv.w);
            }
            ar[i] = v;
        }
#pragma unroll
        for (int i = 0; i < 8; i++) {             // B: 256 rows x 8 q4
            int idx = tid + i * 256;
            int n = idx >> 3, q4 = idx & 7;
            int o = n >> 1, m = n & 1;
            float4 v = make_float4(0.f, 0.f, 0.f, 0.f);
            if (c < 8) {
                v = __ldg((const float4*)((m ? Wu : Wg) + (size_t)(ob + o) * 256 + c * 32) + q4);
            } else if (c == 8) {
                if (!m) v = __ldg((const float4*)(Ag + (size_t)(ob + o) * 32) + q4);
            } else {
                if (m) v = __ldg((const float4*)(Au + (size_t)(ob + o) * 32) + q4);
            }
            br[i] = v;
        }
    };
    auto sts_phase = [&](int c, int buf) {
#pragma unroll
        for (int i = 0; i < 2; i++) {
            int idx = tid + i * 256;
            int row = idx >> 3, q4 = idx & 7;
            float4 v = ar[i];
            if (c < 8) v = mul4(v, sS[row + 1 + roff]);
            stA<K8>(Ab[buf], row, q4, v);
        }
#pragma unroll
        for (int i = 0; i < 8; i++) {
            int idx = tid + i * 256;
            stB<K8>(Bb[buf], idx >> 3, idx & 7, br[i]);
        }
    };
    auto compute = [&](int buf) {
#pragma unroll
        for (int k8 = 0; k8 < K8; k8++) {
            uint32_t a[2][4], bf[8][2];
#pragma unroll
            for (int mi2 = 0; mi2 < 2; mi2++) ldA<K8>(a[mi2], Ab[buf], k8, wm * 2 + mi2, lane);
#pragma unroll
            for (int n2 = 0; n2 < 8; n2 += 2)
                ldB<K8>(bf[n2], bf[n2 + 1], Bb[buf], k8, wn * 8 + n2, lane);
#pragma unroll
            for (int mi2 = 0; mi2 < 2; mi2++)
#pragma unroll
                for (int n2 = 0; n2 < 8; n2++) mma168(acc[mi2][n2], a[mi2], bf[n2]);
        }
    };

    ldg_phase(0);
    sts_phase(0, 0);
    __syncthreads();
    for (int c = 0; c < 10; c++) {
        int buf = c & 1;
        if (c < 9) ldg_phase(c + 1);
        compute(buf);
        if (c < 9) sts_phase(c + 1, buf ^ 1);
        __syncthreads();
    }

#pragma unroll
    for (int mi2 = 0; mi2 < 2; mi2++)
#pragma unroll
        for (int n2 = 0; n2 < 8; n2++) {
            int r0 = t0 + wm * 32 + mi2 * 16 + (lane >> 2);
            int o  = ob + wn * 32 + n2 * 4 + (lane & 3);
            float g0 = acc[mi2][n2][0], u0 = acc[mi2][n2][1];
            hout[(size_t)r0 * 1024 + o] = hin[(size_t)r0 * 1024 + o] + sigf(g0) * u0;
            int r1 = r0 + 8;
            float g1 = acc[mi2][n2][2], u1 = acc[mi2][n2][3];
            hout[(size_t)r1 * 1024 + o] = hin[(size_t)r1 * 1024 + o] + sigf(g1) * u1;
        }
}

// ---------------------------------------------------------------------------
// k_ff_m: CTA = 64 tokens x block b x slice ot (outs {128,128,96}).
// Fused N=256 (n=2oo+m: m=0 ffg, m=1 fff), K=192 = [(h*s)_b(128)|Rg(32)|Rf(32)].
// 256 threads, smem 80 KB -> 2 CTAs/SM.  Epilogue: FF = silu(g)*f (bf16).
// ---------------------------------------------------------------------------
__global__ __launch_bounds__(256, 2)
void k_ff_m(const float* __restrict__ hin, const float* __restrict__ sf,
            const float* __restrict__ Rg,
            const float* __restrict__ Wg, const float* __restrict__ Wf,
            const float* __restrict__ Ag, const float* __restrict__ Af,
            __nv_bfloat16* __restrict__ FF) {
    constexpr int K8 = 4;
    extern __shared__ float sm[];
    __shared__ float sS[64];
    const uint32_t sbase = s2u(sm);
    const uint32_t Ab[2] = { sbase, sbase + 8192 };
    const uint32_t Bb[2] = { sbase + 16384, sbase + 49152 };
    const int tid = threadIdx.x, lane = tid & 31, wid = tid >> 5;
    const int wm = wid >> 2, wn = wid & 3;
    const int t0 = blockIdx.x * 64, b = blockIdx.y, ot = blockIdx.z;
    const int nav = (ot == 2) ? 96 : 128;
    const int obase = b * 352 + ot * 128;

    if (tid < 64) sS[tid] = sf[t0 + tid];
    __syncthreads();

    float acc[2][8][4];
#pragma unroll
    for (int i = 0; i < 2; i++)
#pragma unroll
        for (int j = 0; j < 8; j++)
#pragma unroll
            for (int k = 0; k < 4; k++) acc[i][j][k] = 0.0f;

    float4 ar[2], br[8];

    auto ldg_phase = [&](int c) {
#pragma unroll
        for (int i = 0; i < 2; i++) {
            int idx = tid + i * 256;
            int row = idx >> 3, q4 = idx & 7;
            int tok = t0 + row;
            if (c < 4)
                ar[i] = __ldg((const float4*)(hin + (size_t)tok * 1024 + b * 128 + c * 32) + q4);
            else
                ar[i] = __ldg((const float4*)(Rg + (size_t)tok * 64 + (c - 4) * 32) + q4);
        }
#pragma unroll
        for (int i = 0; i < 8; i++) {
            int idx = tid + i * 256;
            int n = idx >> 3, q4 = idx & 7;
            int oo = n >> 1, m = n & 1;
            float4 v = make_float4(0.f, 0.f, 0.f, 0.f);
            if (oo < nav) {
                int og = obase + oo;
                if (c < 4)
                    v = __ldg((const float4*)((m ? Wf : Wg) + (size_t)og * 128 + c * 32) + q4);
                else if (c == 4) {
                    if (!m) v = __ldg((const float4*)(Ag + (size_t)og * 32) + q4);
                } else {
                    if (m) v = __ldg((const float4*)(Af + (size_t)og * 32) + q4);
                }
            }
            br[i] = v;
        }
    };
    auto sts_phase = [&](int c, int buf) {
#pragma unroll
        for (int i = 0; i < 2; i++) {
            int idx = tid + i * 256;
            int row = idx >> 3, q4 = idx & 7;
            float4 v = ar[i];
            if (c < 4) v = mul4(v, sS[row]);
            stA<K8>(Ab[buf], row, q4, v);
        }
#pragma unroll
        for (int i = 0; i < 8; i++) {
            int idx = tid + i * 256;
            stB<K8>(Bb[buf], idx >> 3, idx & 7, br[i]);
        }
    };
    auto compute = [&](int buf) {
#pragma unroll
        for (int k8 = 0; k8 < K8; k8++) {
            uint32_t a[2][4], bf[8][2];
#pragma unroll
            for (int mi2 = 0; mi2 < 2; mi2++) ldA<K8>(a[mi2], Ab[buf], k8, wm * 2 + mi2, lane);
#pragma unroll
            for (int n2 = 0; n2 < 8; n2 += 2)
                ldB<K8>(bf[n2], bf[n2 + 1], Bb[buf], k8, wn * 8 + n2, lane);
#pragma unroll
            for (int mi2 = 0; mi2 < 2; mi2++)
#pragma unroll
                for (int n2 = 0; n2 < 8; n2++) mma168(acc[mi2][n2], a[mi2], bf[n2]);
        }
    };

    ldg_phase(0);
    sts_phase(0, 0);
    __syncthreads();
    for (int c = 0; c < 6; c++) {
        int buf = c & 1;
        if (c < 5) ldg_phase(c + 1);
        compute(buf);
        if (c < 5) sts_phase(c + 1, buf ^ 1);
        __syncthreads();
    }

#pragma unroll
    for (int mi2 = 0; mi2 < 2; mi2++)
#pragma unroll
        for (int n2 = 0; n2 < 8; n2++) {
            int oo = wn * 32 + n2 * 4 + (lane & 3);
            if (oo < nav) {
                int r0 = t0 + wm * 32 + mi2 * 16 + (lane >> 2);
                float g0 = acc[mi2][n2][0], f0 = acc[mi2][n2][1];
                FF[(size_t)r0 * 2816 + obase + oo] = __float2bfloat16(g0 * sigf(g0) * f0);
                int r1 = r0 + 8;
                float g1 = acc[mi2][n2][2], f1 = acc[mi2][n2][3];
                FF[(size_t)r1 * 2816 + obase + oo] = __float2bfloat16(g1 * sigf(g1) * f1);
            }
        }
}

// ---------------------------------------------------------------------------
// k_out_m: CTA = 128 tokens x block b.  N=128, K=384 = [FF_b(352, bf16)|R(32)].
// 512 threads, 3-phase pipeline.  Epilogue: out = h + y.
// ---------------------------------------------------------------------------
#define OUT_SMEM 65536
__global__ __launch_bounds__(512, 1)
void k_out_m(const __nv_bfloat16* __restrict__ FF, const float* __restrict__ Rg,
             const float* __restrict__ Wp, const float* __restrict__ Ap,
             const float* __restrict__ hin, float* __restrict__ outp) {
    constexpr int K8 = 4;
    extern __shared__ float sm[];
    const uint32_t sbase = s2u(sm);
    const uint32_t Ab[2] = { sbase, sbase + 16384 };
    const uint32_t Bb[2] = { sbase + 32768, sbase + 49152 };
    const int tid = threadIdx.x, lane = tid & 31, wid = tid >> 5;
    const int wm = wid >> 2, wn = wid & 3;
    const int t0 = blockIdx.x * 128, b = blockIdx.y, ob = b * 128;

    float acc[2][4][4];
#pragma unroll
    for (int i = 0; i < 2; i++)
#pragma unroll
        for (int j = 0; j < 4; j++)
#pragma unroll
            for (int k = 0; k < 4; k++) acc[i][j][k] = 0.0f;

    float4 ar[2], br[2];

    auto ldg_phase = [&](int c) {
#pragma unroll
        for (int i = 0; i < 2; i++) {
            int idx = tid + i * 512;
            int row = idx >> 3, q4 = idx & 7;
            int tok = t0 + row;
            if (c < 11)
                ar[i] = ldbf4(FF + (size_t)tok * 2816 + b * 352 + c * 32 + q4 * 4);
            else
                ar[i] = __ldg((const float4*)(Rg + (size_t)tok * 64) + q4);
        }
#pragma unroll
        for (int i = 0; i < 2; i++) {
            int idx = tid + i * 512;
            int n = idx >> 3, q4 = idx & 7;
            if (c < 11)
                br[i] = __ldg((const float4*)(Wp + (size_t)(ob + n) * 352 + c * 32) + q4);
            else
                br[i] = __ldg((const float4*)(Ap + (size_t)(ob + n) * 32) + q4);
        }
    };
    auto sts_phase = [&](int buf) {
#pragma unroll
        for (int i = 0; i < 2; i++) {
            int idx = tid + i * 512;
            stA<K8>(Ab[buf], idx >> 3, idx & 7, ar[i]);
        }
#pragma unroll
        for (int i = 0; i < 2; i++) {
            int idx = tid + i * 512;
            stB<K8>(Bb[buf], idx >> 3, idx & 7, br[i]);
        }
    };
    auto compute = [&](int buf) {
#pragma unroll
        for (int k8 = 0; k8 < K8; k8++) {
            uint32_t a[2][4], bf[4][2];
#pragma unroll
            for (int mi2 = 0; mi2 < 2; mi2++) ldA<K8>(a[mi2], Ab[buf], k8, wm * 2 + mi2, lane);
#pragma unroll
            for (int n2 = 0; n2 < 4; n2 += 2)
                ldB<K8>(bf[n2], bf[n2 + 1], Bb[buf], k8, wn * 4 + n2, lane);
#pragma unroll
            for (int mi2 = 0; mi2 < 2; mi2++)
#pragma unroll
                for (int n2 = 0; n2 < 4; n2++) mma168(acc[mi2][n2], a[mi2], bf[n2]);
        }
    };

    ldg_phase(0);
    sts_phase(0);
    __syncthreads();
    for (int c = 0; c < 12; c++) {
        int buf = c & 1;
        if (c < 11) ldg_phase(c + 1);
        compute(buf);
        if (c < 11) sts_phase(buf ^ 1);
        __syncthreads();
    }

#pragma unroll
    for (int mi2 = 0; mi2 < 2; mi2++)
#pragma unroll
        for (int n2 = 0; n2 < 4; n2++) {
            int r0 = t0 + wm * 32 + mi2 * 16 + (lane >> 2);
            int o  = ob + wn * 32 + n2 * 8 + 2 * (lane & 3);
            float2 h0 = *(const float2*)(hin + (size_t)r0 * 1024 + o);
            *(float2*)(outp + (size_t)r0 * 1024 + o) =
                make_float2(h0.x + acc[mi2][n2][0], h0.y + acc[mi2][n2][1]);
            int r1 = r0 + 8;
            float2 h1 = *(const float2*)(hin + (size_t)r1 * 1024 + o);
            *(float2*)(outp + (size_t)r1 * 1024 + o) =
                make_float2(h1.x + acc[mi2][n2][2], h1.y + acc[mi2][n2][3]);
        }
}

// ---------------------------------------------------------------------------
// Host launcher
// ---------------------------------------------------------------------------
#define RANKPQ_SMEM 98304     // (16K A + 32K B) x2
#define RANK64_SMEM 65536     // (16K A + 16K B) x2
#define RANK32_SMEM 49152     // (16K A +  8K B) x2

extern "C" void kernel_launch(void* const* d_in, const int* in_sizes, int n_in,
                              void* d_out, int out_size) {
    const float* x    = (const float*)d_in[0];
    const float* fgW  = (const float*)d_in[1];
    const float* fgA  = (const float*)d_in[2];
    const float* fgB  = (const float*)d_in[3];
    const float* guW  = (const float*)d_in[4];
    const float* guA  = (const float*)d_in[5];
    const float* guB  = (const float*)d_in[6];
    const float* ffgW = (const float*)d_in[7];
    const float* ffgA = (const float*)d_in[8];
    const float* ffgB = (const float*)d_in[9];
    const float* fffW = (const float*)d_in[10];
    const float* fffA = (const float*)d_in[11];
    const float* fffB = (const float*)d_in[12];
    const float* ffpW = (const float*)d_in[13];
    const float* ffpA = (const float*)d_in[14];
    const float* ffpB = (const float*)d_in[15];
    float* outp = (float*)d_out;

    float *H, *H2, *S, *Rr;
    __nv_bfloat16* FF;
    cudaGetSymbolAddress((void**)&H,  g_H);
    cudaGetSymbolAddress((void**)&H2, g_H2);
    cudaGetSymbolAddress((void**)&S,  g_S);
    cudaGetSymbolAddress((void**)&Rr, g_R);
    cudaGetSymbolAddress((void**)&FF, g_FF);

    cudaFuncSetAttribute(k_iter_m, cudaFuncAttributeMaxDynamicSharedMemorySize, ITER_SMEM);
    cudaFuncSetAttribute(k_ff_m,   cudaFuncAttributeMaxDynamicSharedMemorySize, ITER_SMEM);
    cudaFuncSetAttribute(k_out_m,  cudaFuncAttributeMaxDynamicSharedMemorySize, OUT_SMEM);
    cudaFuncSetAttribute(k_rank_m<128, 1024, 1024, 128, true, false, true>,
                         cudaFuncAttributeMaxDynamicSharedMemorySize, RANKPQ_SMEM);
    cudaFuncSetAttribute(k_rank_m<64, 1024, 1024, 64, true, false, false>,
                         cudaFuncAttributeMaxDynamicSharedMemorySize, RANK64_SMEM);
    cudaFuncSetAttribute(k_rank_m<32, 2816, 2816, 64, false, true, false>,
                         cudaFuncAttributeMaxDynamicSharedMemorySize, RANK32_SMEM);

    // ping-pong: x -> H -> H2 -> H -> H2  (k_iter must not run in-place)
    const float* hcur = x;
    float* hbuf[2] = { H, H2 };
    for (int it = 0; it < 4; it++) {
        float* hnext = hbuf[it & 1];
        // PQ rank also computes S inline (rmsnorm scale) and writes g_S
        k_rank_m<128, 1024, 1024, 128, true, false, true>
            <<<NTOK / 64, 256, RANKPQ_SMEM>>>(hcur, S, fgB, guB, Rr);
        k_iter_m<<<dim3(NTOK / 64, 8), 256, ITER_SMEM>>>(hcur, S, Rr, fgW, guW, fgA, guA, hnext);
        hcur = hnext;
    }
    k_rank_m<64, 1024, 1024, 64, true, false, false>
        <<<NTOK / 64, 256, RANK64_SMEM>>>(hcur, S, ffgB, fffB, Rr);
    k_ff_m<<<dim3(NTOK / 64, 8, 3), 256, ITER_SMEM>>>(hcur, S, Rr, ffgW, fffW, ffgA, fffA, FF);
    k_rank_m<32, 2816, 2816, 64, false, true, false>
        <<<NTOK / 64, 256, RANK32_SMEM>>>(FF, nullptr, ffpB, ffpB, Rr);
    k_out_m<<<dim3(NTOK / 128, 8), 512, OUT_SMEM>>>(FF, Rr, ffpW, ffpA, hcur, outp);
}

// round 17
// speedup vs baseline: 1.7561x; 1.7561x over previous
#include <cuda_runtime.h>
#include <cuda_bf16.h>
#include <math.h>
#include <stdint.h>

// ---------------------------------------------------------------------------
// IterativeBlock on GB300, compute_103-safe.
// Dense GEMMs + rank projections: warp-level mma.sync tf32 (m16n8k8),
// ldmatrix fragment loads, explicit 3-phase pipeline:
//   ldg(c+1)->regs ; compute(c) ; sts(c+1) ; __syncthreads
// Rank reform: R[t] = P[t] + Q[t-1], [P|Q] from a shift-free KD=1024 GEMM.
// rmsnorm: rank kernels compute s[t] INLINE (ssq of streamed h rows),
// apply at their epilogue, and write g_S for iter/ff.  No k_scale kernel.
// Dense kernels: 128-token tiles, 512 threads (RF-bound at 1 CTA/SM; the
// 64-token/2-CTA variant measured L1tex-bound and slower).
// h ping-pongs g_H <-> g_H2.  FF intermediate bf16.
// ---------------------------------------------------------------------------

#define NTOK 16384
#define EPSF 1.1920929e-07f

__device__ float         g_H [NTOK * 1024];
__device__ float         g_H2[NTOK * 1024];
__device__ float         g_S [NTOK];
__device__ float         g_R [NTOK * 128];
__device__ __nv_bfloat16 g_FF[NTOK * 2816];

__device__ __forceinline__ float sigf(float x) { return 1.0f / (1.0f + __expf(-x)); }

__device__ __forceinline__ uint32_t cvt_tf32(float f) {
    uint32_t r; asm("cvt.rna.tf32.f32 %0, %1;" : "=r"(r) : "f"(f)); return r;
}
__device__ __forceinline__ uint32_t s2u(const void* p) {
    return (uint32_t)__cvta_generic_to_shared(p);
}
__device__ __forceinline__ void ldsm4(uint32_t& r0, uint32_t& r1, uint32_t& r2, uint32_t& r3,
                                      uint32_t addr) {
    asm volatile("ldmatrix.sync.aligned.m8n8.x4.shared.b16 {%0,%1,%2,%3}, [%4];"
                 : "=r"(r0), "=r"(r1), "=r"(r2), "=r"(r3) : "r"(addr));
}
__device__ __forceinline__ void mma168(float* c, const uint32_t* a, const uint32_t* b) {
    asm volatile(
        "mma.sync.aligned.m16n8k8.row.col.f32.tf32.tf32.f32 "
        "{%0,%1,%2,%3}, {%4,%5,%6,%7}, {%8,%9}, {%0,%1,%2,%3};"
        : "+f"(c[0]), "+f"(c[1]), "+f"(c[2]), "+f"(c[3])
        : "r"(a[0]), "r"(a[1]), "r"(a[2]), "r"(a[3]), "r"(b[0]), "r"(b[1]));
}

// ---- tile staging / fragment loads ----------------------------------------
// 128-byte ldmatrix blocks = 8 rows x 4 tf32.
//   bidA = ((mi*2+mh)*K8 + k8)*2 + kh,  bidB = (ni*K8 + k8)*2 + r
// Row within a block XOR-swizzled by (bid & 7).
template<int K8>
__device__ __forceinline__ void stA(uint32_t base, int row, int q4, float4 v) {
    int k8 = q4 >> 1, kh = q4 & 1;
    int m8 = row & 7, mh = (row >> 3) & 1, mi = row >> 4;
    int bid = ((mi * 2 + mh) * K8 + k8) * 2 + kh;
    int r = m8 ^ (bid & 7);
    uint32_t addr = base + (uint32_t)(bid * 128 + r * 16);
    asm volatile("st.shared.v4.b32 [%0], {%1,%2,%3,%4};" :: "r"(addr),
                 "r"(cvt_tf32(v.x)), "r"(cvt_tf32(v.y)),
                 "r"(cvt_tf32(v.z)), "r"(cvt_tf32(v.w)) : "memory");
}
template<int K8>
__device__ __forceinline__ void stB(uint32_t base, int n, int q4, float4 v) {
    int k8 = q4 >> 1, r = q4 & 1;
    int n8 = n & 7, ni = n >> 3;
    int bid = (ni * K8 + k8) * 2 + r;
    int rr = n8 ^ (bid & 7);
    uint32_t addr = base + (uint32_t)(bid * 128 + rr * 16);
    asm volatile("st.shared.v4.b32 [%0], {%1,%2,%3,%4};" :: "r"(addr),
                 "r"(cvt_tf32(v.x)), "r"(cvt_tf32(v.y)),
                 "r"(cvt_tf32(v.z)), "r"(cvt_tf32(v.w)) : "memory");
}
template<int K8>
__device__ __forceinline__ void ldA(uint32_t* a, uint32_t base, int k8, int mi, int lane) {
    int j = lane >> 3, mh = j & 1, kh = j >> 1;
    int bid = ((mi * 2 + mh) * K8 + k8) * 2 + kh;
    int r = (lane & 7) ^ (bid & 7);
    ldsm4(a[0], a[1], a[2], a[3], base + (uint32_t)(bid * 128 + r * 16));
}
template<int K8>
__device__ __forceinline__ void ldB(uint32_t* b0, uint32_t* b1, uint32_t base,
                                    int k8, int ni0, int lane) {
    int j = lane >> 3, nio = j >> 1, r = j & 1;
    int bid = ((ni0 + nio) * K8 + k8) * 2 + r;
    int rr = (lane & 7) ^ (bid & 7);
    ldsm4(b0[0], b0[1], b1[0], b1[1], base + (uint32_t)(bid * 128 + rr * 16));
}
__device__ __forceinline__ float4 ldbf4(const __nv_bfloat16* p) {
    uint2 raw = *(const uint2*)p;
    __nv_bfloat162 b0 = *(__nv_bfloat162*)&raw.x;
    __nv_bfloat162 b1 = *(__nv_bfloat162*)&raw.y;
    float2 f0 = __bfloat1622float2(b0), f1 = __bfloat1622float2(b1);
    return make_float4(f0.x, f0.y, f1.x, f1.y);
}
__device__ __forceinline__ float4 mul4(float4 v, float s) {
    return make_float4(v.x * s, v.y * s, v.z * s, v.w * s);
}

// ---------------------------------------------------------------------------
// k_rank_m: R[t, 0:NO] = Bmap @ h_t, scaled by s[t] at the epilogue.
// SCALE: s[t] computed INLINE from ssq of the streamed h rows; written to Sout.
// SPLIT4 (PQ): row n -> (n<64 ? B1 : B2) row (n&31), col-half ((n>>5)&1)*1024.
// else: n<32 -> B1 row n; else B2 row n-32 (row length KD).
// BF16SRC: src is bf16 (no scale).  RST: output row stride.
// CTA = 64 tokens, K-chunk 64, 3-phase pipeline.  256 threads, 4(wm) x 2(wn).
// ---------------------------------------------------------------------------
template<int NO, int KD, int SRCS, int RST, bool SCALE, bool BF16SRC, bool SPLIT4>
__global__ __launch_bounds__(256)
void k_rank_m(const void* __restrict__ srcv, float* __restrict__ Sout,
              const float* __restrict__ B1, const float* __restrict__ B2,
              float* __restrict__ R) {
    constexpr int K8 = 8;                         // chunk = 64 K
    constexpr int NIW = NO / 16;
    constexpr int NB = NO / 16;
    constexpr int ABYTES = 16384;
    constexpr int BBYTES = NO * 64 * 4;
    constexpr int NC = KD / 64;
    extern __shared__ float sm[];
    __shared__ float sSr[64];
    const uint32_t sbase = s2u(sm);
    const int tid = threadIdx.x, lane = tid & 31, wid = tid >> 5;
    const int wm = wid >> 1, wn = wid & 1;
    const int t0 = blockIdx.x * 64;

    float acc[NIW][4];
#pragma unroll
    for (int j = 0; j < NIW; j++)
#pragma unroll
        for (int i = 0; i < 4; i++) acc[j][i] = 0.0f;

    float ssq[4] = {0.f, 0.f, 0.f, 0.f};
    float4 ar[4], br[NB];

    auto ldg_phase = [&](int c) {
#pragma unroll
        for (int i = 0; i < 4; i++) {             // A: 64 rows x 16 q4
            int idx = tid + i * 256;
            int row = idx >> 4, q4 = idx & 15;
            int tok = t0 + row;
            if (BF16SRC)
                ar[i] = ldbf4((const __nv_bfloat16*)srcv + (size_t)tok * SRCS + c * 64 + q4 * 4);
            else
                ar[i] = __ldg((const float4*)((const float*)srcv +
                              (size_t)tok * SRCS + c * 64) + q4);
        }
#pragma unroll
        for (int i = 0; i < NB; i++) {            // B: NO rows x 16 q4
            int idx = tid + i * 256;
            int n = idx >> 4, q4 = idx & 15;
            const float* Bp;
            if (SPLIT4)
                Bp = ((n < 64) ? B1 : B2) + (size_t)(n & 31) * 2048 + ((n >> 5) & 1) * 1024;
            else
                Bp = (n < 32) ? (B1 + (size_t)n * KD) : (B2 + (size_t)(n - 32) * KD);
            br[i] = __ldg((const float4*)(Bp + c * 64) + q4);
        }
    };
    auto sts_phase = [&](int buf) {
        const uint32_t Ab = sbase + buf * (ABYTES + BBYTES);
        const uint32_t Bb = Ab + ABYTES;
#pragma unroll
        for (int i = 0; i < 4; i++) {
            int idx = tid + i * 256;
            if (SCALE) {
                ssq[i] = fmaf(ar[i].x, ar[i].x, ssq[i]);
                ssq[i] = fmaf(ar[i].y, ar[i].y, ssq[i]);
                ssq[i] = fmaf(ar[i].z, ar[i].z, ssq[i]);
                ssq[i] = fmaf(ar[i].w, ar[i].w, ssq[i]);
            }
            stA<K8>(Ab, idx >> 4, idx & 15, ar[i]);
        }
#pragma unroll
        for (int i = 0; i < NB; i++) {
            int idx = tid + i * 256;
            stB<K8>(Bb, idx >> 4, idx & 15, br[i]);
        }
    };
    auto compute = [&](int buf) {
        const uint32_t Ab = sbase + buf * (ABYTES + BBYTES);
        const uint32_t Bb = Ab + ABYTES;
#pragma unroll
        for (int k8 = 0; k8 < K8; k8++) {
            uint32_t a[4], bf[NIW][2];
            ldA<K8>(a, Ab, k8, wm, lane);
#pragma unroll
            for (int n2 = 0; n2 < NIW; n2 += 2)
                ldB<K8>(bf[n2], bf[n2 + 1], Bb, k8, wn * NIW + n2, lane);
#pragma unroll
            for (int n2 = 0; n2 < NIW; n2++) mma168(acc[n2], a, bf[n2]);
        }
    };

    ldg_phase(0);
    sts_phase(0);
    __syncthreads();
    for (int c = 0; c < NC; c++) {
        int buf = c & 1;
        if (c + 1 < NC) ldg_phase(c + 1);
        compute(buf);
        if (c + 1 < NC) sts_phase(buf ^ 1);
        __syncthreads();
    }

    if (SCALE) {
        // thread tid = g*16+q4 holds partial ssq for rows {g, g+16, g+32, g+48}
#pragma unroll
        for (int i = 0; i < 4; i++) {
            float v = ssq[i];
#pragma unroll
            for (int off = 8; off; off >>= 1) v += __shfl_xor_sync(0xffffffffu, v, off);
            if ((lane & 15) == 0) {
                int row = (tid >> 4) + i * 16;
                float sc = rsqrtf(v * (1.0f / 1024.0f) + EPSF);
                sSr[row] = sc;
                Sout[t0 + row] = sc;
            }
        }
        __syncthreads();
    }

    const int lr0 = wm * 16 + (lane >> 2);
    const float s0 = SCALE ? sSr[lr0] : 1.0f;
    const float s1 = SCALE ? sSr[lr0 + 8] : 1.0f;
    const int r0 = t0 + lr0, r1 = r0 + 8;
#pragma unroll
    for (int n2 = 0; n2 < NIW; n2++) {
        int o = wn * (NO / 2) + n2 * 8 + 2 * (lane & 3);
        *(float2*)(R + (size_t)r0 * RST + o) = make_float2(acc[n2][0] * s0, acc[n2][1] * s0);
        *(float2*)(R + (size_t)r1 * RST + o) = make_float2(acc[n2][2] * s1, acc[n2][3] * s1);
    }
}

// ---------------------------------------------------------------------------
// k_iter_m: CTA = 128 tokens x block b. Fused N=256 (n=2o+m: m=0 fg, m=1 gu),
// K=320 = [(h*s)_b slice (256) | Rg(32) | Ru(32)] where
// Rg[t] = PQ[t,0:32]+PQ[t-1,32:64], Ru[t] = PQ[t,64:96]+PQ[t-1,96:128].
// 512 threads = 4x4 warps, 3-phase pipeline.
// Epilogue: hout = hin + sigmoid(g)*u  (hin != hout).
// smem: A 16K x2 + B 32K x2 = 96 KB.
// ---------------------------------------------------------------------------
#define ITER_SMEM 98304
__global__ __launch_bounds__(512, 1)
void k_iter_m(const float* __restrict__ hin, const float* __restrict__ sf,
              const float* __restrict__ PQ,
              const float* __restrict__ Wg, const float* __restrict__ Wu,
              const float* __restrict__ Ag, const float* __restrict__ Au,
              float* __restrict__ hout) {
    constexpr int K8 = 4;
    extern __shared__ float sm[];
    __shared__ float sS[129];
    const uint32_t sbase = s2u(sm);
    const uint32_t Ab[2] = { sbase, sbase + 16384 };
    const uint32_t Bb[2] = { sbase + 32768, sbase + 65536 };
    const int tid = threadIdx.x, lane = tid & 31, wid = tid >> 5;
    const int wm = wid >> 2, wn = wid & 3;
    const int t0 = blockIdx.x * 128, b = blockIdx.y;
    const int roff = (b < 4) ? 0 : -1, cbase = (b & 3) * 256, ob = b * 128;

    if (tid < 129) {
        int tk = t0 - 1 + tid;
        sS[tid] = (tk >= 0) ? sf[tk] : 0.0f;
    }
    __syncthreads();

    float acc[2][8][4];
#pragma unroll
    for (int i = 0; i < 2; i++)
#pragma unroll
        for (int j = 0; j < 8; j++)
#pragma unroll
            for (int k = 0; k < 4; k++) acc[i][j][k] = 0.0f;

    float4 ar[2], br[4];

    auto ldg_phase = [&](int c) {
#pragma unroll
        for (int i = 0; i < 2; i++) {             // A: 128 rows x 8 q4
            int idx = tid + i * 512;
            int row = idx >> 3, q4 = idx & 7;
            int tok = t0 + row;
            float4 v = make_float4(0.f, 0.f, 0.f, 0.f);
            if (c < 8) {
                if (roff == 0 || (tok & 2047) != 0)
                    v = __ldg((const float4*)(hin + (size_t)(tok + roff) * 1024
                                              + cbase + c * 32) + q4);
            } else {
                int half = (c == 8) ? 0 : 64;
                float4 p = __ldg((const float4*)(PQ + (size_t)tok * 128 + half) + q4);
                float4 qv = make_float4(0.f, 0.f, 0.f, 0.f);
                if ((tok & 2047) != 0)
                    qv = __ldg((const float4*)(PQ + (size_t)(tok - 1) * 128 + half + 32) + q4);
                v = make_float4(p.x + qv.x, p.y + qv.y, p.z + qv.z, p.w + qv.w);
            }
            ar[i] = v;
        }
#pragma unroll
        for (int i = 0; i < 4; i++) {             // B: 256 rows x 8 q4
            int idx = tid + i * 512;
            int n = idx >> 3, q4 = idx & 7;
            int o = n >> 1, m = n & 1;
            float4 v = make_float4(0.f, 0.f, 0.f, 0.f);
            if (c < 8) {
                v = __ldg((const float4*)((m ? Wu : Wg) + (size_t)(ob + o) * 256 + c * 32) + q4);
            } else if (c == 8) {
                if (!m) v = __ldg((const float4*)(Ag + (size_t)(ob + o) * 32) + q4);
            } else {
                if (m) v = __ldg((const float4*)(Au + (size_t)(ob + o) * 32) + q4);
            }
            br[i] = v;
        }
    };
    auto sts_phase = [&](int c, int buf) {
#pragma unroll
        for (int i = 0; i < 2; i++) {
            int idx = tid + i * 512;
            int row = idx >> 3, q4 = idx & 7;
            float4 v = ar[i];
            if (c < 8) v = mul4(v, sS[row + 1 + roff]);
            stA<K8>(Ab[buf], row, q4, v);
        }
#pragma unroll
        for (int i = 0; i < 4; i++) {
            int idx = tid + i * 512;
            stB<K8>(Bb[buf], idx >> 3, idx & 7, br[i]);
        }
    };
    auto compute = [&](int buf) {
#pragma unroll
        for (int k8 = 0; k8 < K8; k8++) {
            uint32_t a[2][4], bf[8][2];
#pragma unroll
            for (int mi2 = 0; mi2 < 2; mi2++) ldA<K8>(a[mi2], Ab[buf], k8, wm * 2 + mi2, lane);
#pragma unroll
            for (int n2 = 0; n2 < 8; n2 += 2)
                ldB<K8>(bf[n2], bf[n2 + 1], Bb[buf], k8, wn * 8 + n2, lane);
#pragma unroll
            for (int mi2 = 0; mi2 < 2; mi2++)
#pragma unroll
                for (int n2 = 0; n2 < 8; n2++) mma168(acc[mi2][n2], a[mi2], bf[n2]);
        }
    };

    ldg_phase(0);
    sts_phase(0, 0);
    __syncthreads();
    for (int c = 0; c < 10; c++) {
        int buf = c & 1;
        if (c < 9) ldg_phase(c + 1);
        compute(buf);
        if (c < 9) sts_phase(c + 1, buf ^ 1);
        __syncthreads();
    }

#pragma unroll
    for (int mi2 = 0; mi2 < 2; mi2++)
#pragma unroll
        for (int n2 = 0; n2 < 8; n2++) {
            int r0 = t0 + wm * 32 + mi2 * 16 + (lane >> 2);
            int o  = ob + wn * 32 + n2 * 4 + (lane & 3);
            float g0 = acc[mi2][n2][0], u0 = acc[mi2][n2][1];
            hout[(size_t)r0 * 1024 + o] = hin[(size_t)r0 * 1024 + o] + sigf(g0) * u0;
            int r1 = r0 + 8;
            float g1 = acc[mi2][n2][2], u1 = acc[mi2][n2][3];
            hout[(size_t)r1 * 1024 + o] = hin[(size_t)r1 * 1024 + o] + sigf(g1) * u1;
        }
}

// ---------------------------------------------------------------------------
// k_ff_m: CTA = 128 tokens x block b x slice ot (outs {128,128,96}).
// Fused N=256 (n=2oo+m: m=0 ffg, m=1 fff), K=192 = [(h*s)_b(128)|Rg(32)|Rf(32)].
// 512 threads, 3-phase pipeline.  Epilogue: FF = silu(g)*f (bf16).
// ---------------------------------------------------------------------------
__global__ __launch_bounds__(512, 1)
void k_ff_m(const float* __restrict__ hin, const float* __restrict__ sf,
            const float* __restrict__ Rg,
            const float* __restrict__ Wg, const float* __restrict__ Wf,
            const float* __restrict__ Ag, const float* __restrict__ Af,
            __nv_bfloat16* __restrict__ FF) {
    constexpr int K8 = 4;
    extern __shared__ float sm[];
    __shared__ float sS[128];
    const uint32_t sbase = s2u(sm);
    const uint32_t Ab[2] = { sbase, sbase + 16384 };
    const uint32_t Bb[2] = { sbase + 32768, sbase + 65536 };
    const int tid = threadIdx.x, lane = tid & 31, wid = tid >> 5;
    const int wm = wid >> 2, wn = wid & 3;
    const int t0 = blockIdx.x * 128, b = blockIdx.y, ot = blockIdx.z;
    const int nav = (ot == 2) ? 96 : 128;
    const int obase = b * 352 + ot * 128;

    if (tid < 128) sS[tid] = sf[t0 + tid];
    __syncthreads();

    float acc[2][8][4];
#pragma unroll
    for (int i = 0; i < 2; i++)
#pragma unroll
        for (int j = 0; j < 8; j++)
#pragma unroll
            for (int k = 0; k < 4; k++) acc[i][j][k] = 0.0f;

    float4 ar[2], br[4];

    auto ldg_phase = [&](int c) {
#pragma unroll
        for (int i = 0; i < 2; i++) {
            int idx = tid + i * 512;
            int row = idx >> 3, q4 = idx & 7;
            int tok = t0 + row;
            if (c < 4)
                ar[i] = __ldg((const float4*)(hin + (size_t)tok * 1024 + b * 128 + c * 32) + q4);
            else
                ar[i] = __ldg((const float4*)(Rg + (size_t)tok * 64 + (c - 4) * 32) + q4);
        }
#pragma unroll
        for (int i = 0; i < 4; i++) {
            int idx = tid + i * 512;
            int n = idx >> 3, q4 = idx & 7;
            int oo = n >> 1, m = n & 1;
            float4 v = make_float4(0.f, 0.f, 0.f, 0.f);
            if (oo < nav) {
                int og = obase + oo;
                if (c < 4)
                    v = __ldg((const float4*)((m ? Wf : Wg) + (size_t)og * 128 + c * 32) + q4);
                else if (c == 4) {
                    if (!m) v = __ldg((const float4*)(Ag + (size_t)og * 32) + q4);
                } else {
                    if (m) v = __ldg((const float4*)(Af + (size_t)og * 32) + q4);
                }
            }
            br[i] = v;
        }
    };
    auto sts_phase = [&](int c, int buf) {
#pragma unroll
        for (int i = 0; i < 2; i++) {
            int idx = tid + i * 512;
            int row = idx >> 3, q4 = idx & 7;
            float4 v = ar[i];
            if (c < 4) v = mul4(v, sS[row]);
            stA<K8>(Ab[buf], row, q4, v);
        }
#pragma unroll
        for (int i = 0; i < 4; i++) {
            int idx = tid + i * 512;
            stB<K8>(Bb[buf], idx >> 3, idx & 7, br[i]);
        }
    };
    auto compute = [&](int buf) {
#pragma unroll
        for (int k8 = 0; k8 < K8; k8++) {
            uint32_t a[2][4], bf[8][2];
#pragma unroll
            for (int mi2 = 0; mi2 < 2; mi2++) ldA<K8>(a[mi2], Ab[buf], k8, wm * 2 + mi2, lane);
#pragma unroll
            for (int n2 = 0; n2 < 8; n2 += 2)
                ldB<K8>(bf[n2], bf[n2 + 1], Bb[buf], k8, wn * 8 + n2, lane);
#pragma unroll
            for (int mi2 = 0; mi2 < 2; mi2++)
#pragma unroll
                for (int n2 = 0; n2 < 8; n2++) mma168(acc[mi2][n2], a[mi2], bf[n2]);
        }
    };

    ldg_phase(0);
    sts_phase(0, 0);
    __syncthreads();
    for (int c = 0; c < 6; c++) {
        int buf = c & 1;
        if (c < 5) ldg_phase(c + 1);
        compute(buf);
        if (c < 5) sts_phase(c + 1, buf ^ 1);
        __syncthreads();
    }

#pragma unroll
    for (int mi2 = 0; mi2 < 2; mi2++)
#pragma unroll
        for (int n2 = 0; n2 < 8; n2++) {
            int oo = wn * 32 + n2 * 4 + (lane & 3);
            if (oo < nav) {
                int r0 = t0 + wm * 32 + mi2 * 16 + (lane >> 2);
                float g0 = acc[mi2][n2][0], f0 = acc[mi2][n2][1];
                FF[(size_t)r0 * 2816 + obase + oo] = __float2bfloat16(g0 * sigf(g0) * f0);
                int r1 = r0 + 8;
                float g1 = acc[mi2][n2][2], f1 = acc[mi2][n2][3];
                FF[(size_t)r1 * 2816 + obase + oo] = __float2bfloat16(g1 * sigf(g1) * f1);
            }
        }
}

// ---------------------------------------------------------------------------
// k_out_m: CTA = 128 tokens x block b.  N=128, K=384 = [FF_b(352, bf16)|R(32)].
// 512 threads, 3-phase pipeline.  Epilogue: out = h + y.
// ---------------------------------------------------------------------------
#define OUT_SMEM 65536
__global__ __launch_bounds__(512, 1)
void k_out_m(const __nv_bfloat16* __restrict__ FF, const float* __restrict__ Rg,
             const float* __restrict__ Wp, const float* __restrict__ Ap,
             const float* __restrict__ hin, float* __restrict__ outp) {
    constexpr int K8 = 4;
    extern __shared__ float sm[];
    const uint32_t sbase = s2u(sm);
    const uint32_t Ab[2] = { sbase, sbase + 16384 };
    const uint32_t Bb[2] = { sbase + 32768, sbase + 49152 };
    const int tid = threadIdx.x, lane = tid & 31, wid = tid >> 5;
    const int wm = wid >> 2, wn = wid & 3;
    const int t0 = blockIdx.x * 128, b = blockIdx.y, ob = b * 128;

    float acc[2][4][4];
#pragma unroll
    for (int i = 0; i < 2; i++)
#pragma unroll
        for (int j = 0; j < 4; j++)
#pragma unroll
            for (int k = 0; k < 4; k++) acc[i][j][k] = 0.0f;

    float4 ar[2], br[2];

    auto ldg_phase = [&](int c) {
#pragma unroll
        for (int i = 0; i < 2; i++) {
            int idx = tid + i * 512;
            int row = idx >> 3, q4 = idx & 7;
            int tok = t0 + row;
            if (c < 11)
                ar[i] = ldbf4(FF + (size_t)tok * 2816 + b * 352 + c * 32 + q4 * 4);
            else
                ar[i] = __ldg((const float4*)(Rg + (size_t)tok * 64) + q4);
        }
#pragma unroll
        for (int i = 0; i < 2; i++) {
            int idx = tid + i * 512;
            int n = idx >> 3, q4 = idx & 7;
            if (c < 11)
                br[i] = __ldg((const float4*)(Wp + (size_t)(ob + n) * 352 + c * 32) + q4);
            else
                br[i] = __ldg((const float4*)(Ap + (size_t)(ob + n) * 32) + q4);
        }
    };
    auto sts_phase = [&](int buf) {
#pragma unroll
        for (int i = 0; i < 2; i++) {
            int idx = tid + i * 512;
            stA<K8>(Ab[buf], idx >> 3, idx & 7, ar[i]);
        }
#pragma unroll
        for (int i = 0; i < 2; i++) {
            int idx = tid + i * 512;
            stB<K8>(Bb[buf], idx >> 3, idx & 7, br[i]);
        }
    };
    auto compute = [&](int buf) {
#pragma unroll
        for (int k8 = 0; k8 < K8; k8++) {
            uint32_t a[2][4], bf[4][2];
#pragma unroll
            for (int mi2 = 0; mi2 < 2; mi2++) ldA<K8>(a[mi2], Ab[buf], k8, wm * 2 + mi2, lane);
#pragma unroll
            for (int n2 = 0; n2 < 4; n2 += 2)
                ldB<K8>(bf[n2], bf[n2 + 1], Bb[buf], k8, wn * 4 + n2, lane);
#pragma unroll
            for (int mi2 = 0; mi2 < 2; mi2++)
#pragma unroll
                for (int n2 = 0; n2 < 4; n2++) mma168(acc[mi2][n2], a[mi2], bf[n2]);
        }
    };

    ldg_phase(0);
    sts_phase(0);
    __syncthreads();
    for (int c = 0; c < 12; c++) {
        int buf = c & 1;
        if (c < 11) ldg_phase(c + 1);
        compute(buf);
        if (c < 11) sts_phase(buf ^ 1);
        __syncthreads();
    }

#pragma unroll
    for (int mi2 = 0; mi2 < 2; mi2++)
#pragma unroll
        for (int n2 = 0; n2 < 4; n2++) {
            int r0 = t0 + wm * 32 + mi2 * 16 + (lane >> 2);
            int o  = ob + wn * 32 + n2 * 8 + 2 * (lane & 3);
            float2 h0 = *(const float2*)(hin + (size_t)r0 * 1024 + o);
            *(float2*)(outp + (size_t)r0 * 1024 + o) =
                make_float2(h0.x + acc[mi2][n2][0], h0.y + acc[mi2][n2][1]);
            int r1 = r0 + 8;
            float2 h1 = *(const float2*)(hin + (size_t)r1 * 1024 + o);
            *(float2*)(outp + (size_t)r1 * 1024 + o) =
                make_float2(h1.x + acc[mi2][n2][2], h1.y + acc[mi2][n2][3]);
        }
}

// ---------------------------------------------------------------------------
// Host launcher
// ---------------------------------------------------------------------------
#define RANKPQ_SMEM 98304     // (16K A + 32K B) x2
#define RANK64_SMEM 65536     // (16K A + 16K B) x2
#define RANK32_SMEM 49152     // (16K A +  8K B) x2

extern "C" void kernel_launch(void* const* d_in, const int* in_sizes, int n_in,
                              void* d_out, int out_size) {
    const float* x    = (const float*)d_in[0];
    const float* fgW  = (const float*)d_in[1];
    const float* fgA  = (const float*)d_in[2];
    const float* fgB  = (const float*)d_in[3];
    const float* guW  = (const float*)d_in[4];
    const float* guA  = (const float*)d_in[5];
    const float* guB  = (const float*)d_in[6];
    const float* ffgW = (const float*)d_in[7];
    const float* ffgA = (const float*)d_in[8];
    const float* ffgB = (const float*)d_in[9];
    const float* fffW = (const float*)d_in[10];
    const float* fffA = (const float*)d_in[11];
    const float* fffB = (const float*)d_in[12];
    const float* ffpW = (const float*)d_in[13];
    const float* ffpA = (const float*)d_in[14];
    const float* ffpB = (const float*)d_in[15];
    float* outp = (float*)d_out;

    float *H, *H2, *S, *Rr;
    __nv_bfloat16* FF;
    cudaGetSymbolAddress((void**)&H,  g_H);
    cudaGetSymbolAddress((void**)&H2, g_H2);
    cudaGetSymbolAddress((void**)&S,  g_S);
    cudaGetSymbolAddress((void**)&Rr, g_R);
    cudaGetSymbolAddress((void**)&FF, g_FF);

    cudaFuncSetAttribute(k_iter_m, cudaFuncAttributeMaxDynamicSharedMemorySize, ITER_SMEM);
    cudaFuncSetAttribute(k_ff_m,   cudaFuncAttributeMaxDynamicSharedMemorySize, ITER_SMEM);
    cudaFuncSetAttribute(k_out_m,  cudaFuncAttributeMaxDynamicSharedMemorySize, OUT_SMEM);
    cudaFuncSetAttribute(k_rank_m<128, 1024, 1024, 128, true, false, true>,
                         cudaFuncAttributeMaxDynamicSharedMemorySize, RANKPQ_SMEM);
    cudaFuncSetAttribute(k_rank_m<64, 1024, 1024, 64, true, false, false>,
                         cudaFuncAttributeMaxDynamicSharedMemorySize, RANK64_SMEM);
    cudaFuncSetAttribute(k_rank_m<32, 2816, 2816, 64, false, true, false>,
                         cudaFuncAttributeMaxDynamicSharedMemorySize, RANK32_SMEM);

    // ping-pong: x -> H -> H2 -> H -> H2  (k_iter must not run in-place)
    const float* hcur = x;
    float* hbuf[2] = { H, H2 };
    for (int it = 0; it < 4; it++) {
        float* hnext = hbuf[it & 1];
        // PQ rank also computes S inline (rmsnorm scale) and writes g_S
        k_rank_m<128, 1024, 1024, 128, true, false, true>
            <<<NTOK / 64, 256, RANKPQ_SMEM>>>(hcur, S, fgB, guB, Rr);
        k_iter_m<<<dim3(NTOK / 128, 8), 512, ITER_SMEM>>>(hcur, S, Rr, fgW, guW, fgA, guA, hnext);
        hcur = hnext;
    }
    k_rank_m<64, 1024, 1024, 64, true, false, false>
        <<<NTOK / 64, 256, RANK64_SMEM>>>(hcur, S, ffgB, fffB, Rr);
    k_ff_m<<<dim3(NTOK / 128, 8, 3), 512, ITER_SMEM>>>(hcur, S, Rr, ffgW, fffW, ffgA, fffA, FF);
    k_rank_m<32, 2816, 2816, 64, false, true, false>
        <<<NTOK / 64, 256, RANK32_SMEM>>>(FF, nullptr, ffpB, ffpB, Rr);
    k_out_m<<<dim3(NTOK / 128, 8), 512, OUT_SMEM>>>(FF, Rr, ffpW, ffpA, hcur, outp);
}